// round 6
// baseline (speedup 1.0000x reference)
#include <cuda_runtime.h>
#include <cuda_bf16.h>
#include <cstdint>
#include <math.h>

#define BB 4
#define CC 512
#define SS 2048
#define HH 8
#define DD 64
#define NPB (CC*SS)

typedef __nv_bfloat16 bf16;

// softmax scale applied at ex2: p = ex2(score * 0.125 * log2(e))
#define SC_LOG2E 0.18033688011112042f

// ---------------- static device scratch ----------------
__device__ float g_part[128 * 2];
__device__ float g_stats[BB * 2];
__device__ bf16 g_h[BB * SS * CC];          // normalized, [B,S,C]
__device__ bf16 g_w[4 * CC * CC];           // wq,wk,wv,wo bf16
__device__ uint8_t g_q[BB * HH * SS * DD];  // e4m3 [B,H,S,D]
__device__ uint8_t g_k[BB * HH * SS * DD];  // e4m3 [B,H,S,D]
__device__ uint8_t g_vt[BB * HH * DD * SS]; // e4m3 [B,H,D,S] (transposed)
__device__ bf16 g_o[BB * SS * CC];          // attention out, [B,S,C]

// ---------------- low-level helpers ----------------
__device__ __forceinline__ uint32_t smem_u32(const void* p) {
    uint32_t a;
    asm("{ .reg .u64 t; cvta.to.shared.u64 t, %1; cvt.u32.u64 %0, t; }" : "=r"(a) : "l"(p));
    return a;
}
__device__ __forceinline__ void ldsm4(uint32_t* r, uint32_t addr) {
    asm volatile("ldmatrix.sync.aligned.m8n8.x4.shared.b16 {%0,%1,%2,%3}, [%4];"
                 : "=r"(r[0]), "=r"(r[1]), "=r"(r[2]), "=r"(r[3]) : "r"(addr));
}
__device__ __forceinline__ void mma16816(float* c, const uint32_t* a, uint32_t b0, uint32_t b1) {
    asm volatile("mma.sync.aligned.m16n8k16.row.col.f32.bf16.bf16.f32 "
                 "{%0,%1,%2,%3}, {%4,%5,%6,%7}, {%8,%9}, {%0,%1,%2,%3};"
                 : "+f"(c[0]), "+f"(c[1]), "+f"(c[2]), "+f"(c[3])
                 : "r"(a[0]), "r"(a[1]), "r"(a[2]), "r"(a[3]), "r"(b0), "r"(b1));
}
__device__ __forceinline__ void mma_fp8(float* c, const uint32_t* a, uint32_t b0, uint32_t b1) {
    asm volatile("mma.sync.aligned.m16n8k32.row.col.f32.e4m3.e4m3.f32 "
                 "{%0,%1,%2,%3}, {%4,%5,%6,%7}, {%8,%9}, {%0,%1,%2,%3};"
                 : "+f"(c[0]), "+f"(c[1]), "+f"(c[2]), "+f"(c[3])
                 : "r"(a[0]), "r"(a[1]), "r"(a[2]), "r"(a[3]), "r"(b0), "r"(b1));
}
__device__ __forceinline__ uint32_t pack_bf16x2(float lo, float hi) {
    uint32_t r;
    asm("cvt.rn.bf16x2.f32 %0, %1, %2;" : "=r"(r) : "f"(hi), "f"(lo));
    return r;
}
__device__ __forceinline__ uint16_t f2e4m3x2(float lo, float hi) {
    uint16_t r;
    asm("cvt.rn.satfinite.e4m3x2.f32 %0, %1, %2;" : "=h"(r) : "f"(hi), "f"(lo));
    return r;
}
__device__ __forceinline__ float ex2(float x) {
    float r;
    asm("ex2.approx.f32 %0, %1;" : "=f"(r) : "f"(x));
    return r;
}
__device__ __forceinline__ void sts16(uint32_t addr, uint16_t v) {
    asm volatile("st.shared.b16 [%0], %1;" :: "r"(addr), "h"(v));
}
__device__ __forceinline__ void cp16(uint32_t dst, const void* src) {
    asm volatile("cp.async.cg.shared.global [%0], [%1], 16;" :: "r"(dst), "l"(src));
}
#define CP_COMMIT() asm volatile("cp.async.commit_group;" ::: "memory")
#define CP_WAIT0()  asm volatile("cp.async.wait_group 0;" ::: "memory")
#define CP_WAIT2()  asm volatile("cp.async.wait_group 2;" ::: "memory")

// ---------------- fused: GroupNorm partials + weight bf16 convert ----------------
__global__ void prep(const float* __restrict__ x,
                     const float* __restrict__ wq, const float* __restrict__ wk,
                     const float* __restrict__ wv, const float* __restrict__ wo) {
    if (blockIdx.x >= 128) {
        int i = (blockIdx.x - 128) * 256 + threadIdx.x;
        g_w[0 * CC * CC + i] = __float2bfloat16(wq[i]);
        g_w[1 * CC * CC + i] = __float2bfloat16(wk[i]);
        g_w[2 * CC * CC + i] = __float2bfloat16(wv[i]);
        g_w[3 * CC * CC + i] = __float2bfloat16(wo[i]);
        return;
    }
    int b = blockIdx.x >> 5;
    int chunk = blockIdx.x & 31;
    const float4* p = (const float4*)(x + (size_t)b * NPB + (size_t)chunk * 32768);
    float s = 0.f, s2 = 0.f;
    for (int i = threadIdx.x; i < 8192; i += 256) {
        float4 v = p[i];
        s += v.x + v.y + v.z + v.w;
        s2 += v.x * v.x + v.y * v.y + v.z * v.z + v.w * v.w;
    }
    __shared__ float sh[256], sh2[256];
    sh[threadIdx.x] = s; sh2[threadIdx.x] = s2;
    __syncthreads();
    for (int off = 128; off > 0; off >>= 1) {
        if (threadIdx.x < off) {
            sh[threadIdx.x] += sh[threadIdx.x + off];
            sh2[threadIdx.x] += sh2[threadIdx.x + off];
        }
        __syncthreads();
    }
    if (threadIdx.x == 0) {
        g_part[blockIdx.x * 2 + 0] = sh[0];
        g_part[blockIdx.x * 2 + 1] = sh2[0];
    }
}

__global__ void gn_finalize() {
    int b = threadIdx.x;
    if (b < BB) {
        float s = 0.f, s2 = 0.f;
        for (int c = 0; c < 32; c++) {
            s  += g_part[(b * 32 + c) * 2 + 0];
            s2 += g_part[(b * 32 + c) * 2 + 1];
        }
        float mean = s / (float)NPB;
        float var = s2 / (float)NPB - mean * mean;
        g_stats[b * 2 + 0] = mean;
        g_stats[b * 2 + 1] = rsqrtf(var + 1e-5f);
    }
}

// ---------------- normalize + transpose [B,C,S] -> bf16 [B,S,C] ----------------
__global__ void norm_convert(const float* __restrict__ x,
                             const float* __restrict__ gw,
                             const float* __restrict__ gb) {
    __shared__ float tile[32][33];
    int b = blockIdx.z;
    int c0 = blockIdx.y * 32;
    int s0 = blockIdx.x * 32;
    float mean = g_stats[b * 2 + 0];
    float inv  = g_stats[b * 2 + 1];
    int c = c0 + threadIdx.y;
    float scale = gw[c] * inv;
    float shift = gb[c] - mean * scale;
    float v = x[((size_t)b * CC + c) * SS + s0 + threadIdx.x];
    tile[threadIdx.y][threadIdx.x] = v * scale + shift;
    __syncthreads();
    g_h[((size_t)b * SS + s0 + threadIdx.y) * CC + c0 + threadIdx.x] =
        __float2bfloat16(tile[threadIdx.x][threadIdx.y]);
}

// ---------------- HMMA bf16 NT GEMM core, 4-stage cp.async ----------------
#define GST 40
#define GTB (128 * GST * 2)
#define G_SMEM_BYTES (8 * GTB)

__device__ __forceinline__ void gemm_core(const bf16* __restrict__ A,
                                          const bf16* __restrict__ W,
                                          int m0, int n0, float c[2][8][4],
                                          char* smem) {
    int tid = threadIdx.x;
    int lane = tid & 31;
    int wid = tid >> 5;
    int wm = wid >> 1, wn = wid & 1;
    uint32_t sA = smem_u32(smem);
    uint32_t sB = sA + 4 * GTB;

#pragma unroll
    for (int i = 0; i < 2; i++)
#pragma unroll
        for (int j = 0; j < 8; j++)
#pragma unroll
            for (int k = 0; k < 4; k++) c[i][j][k] = 0.f;

    int r = tid >> 1, cseg = (tid & 1) * 16;
    const bf16* Ag = A + (size_t)(m0 + r) * 512 + cseg;
    const bf16* Wg = W + (size_t)(n0 + r) * 512 + cseg;
    uint32_t dOff = (uint32_t)(r * GST + cseg) * 2;

#define GPF(kt) do { \
        uint32_t _b = (uint32_t)((kt) & 3) * GTB; \
        const bf16* _An = Ag + (kt) * 32; \
        const bf16* _Wn = Wg + (kt) * 32; \
        cp16(sA + _b + dOff,      _An); \
        cp16(sA + _b + dOff + 16, _An + 8); \
        cp16(sB + _b + dOff,      _Wn); \
        cp16(sB + _b + dOff + 16, _Wn + 8); \
        CP_COMMIT(); \
    } while (0)

    GPF(0); GPF(1); GPF(2);

    for (int kt = 0; kt < 16; kt++) {
        CP_WAIT2();
        __syncthreads();
        if (kt < 13) GPF(kt + 3); else CP_COMMIT();
        uint32_t bo = (uint32_t)(kt & 3) * GTB;
#pragma unroll
        for (int ks = 0; ks < 2; ks++) {
            uint32_t a[2][4];
#pragma unroll
            for (int mt = 0; mt < 2; mt++) {
                uint32_t row = wm * 32 + mt * 16 + (lane & 15);
                uint32_t col = ks * 16 + (lane >> 4) * 8;
                ldsm4(a[mt], sA + bo + (row * GST + col) * 2);
            }
#pragma unroll
            for (int p = 0; p < 4; p++) {
                uint32_t t4[4];
                uint32_t row = wn * 64 + p * 16 + (lane & 7) + ((lane >> 4) << 3);
                uint32_t col = ks * 16 + (((lane >> 3) & 1) << 3);
                ldsm4(t4, sB + bo + (row * GST + col) * 2);
#pragma unroll
                for (int mt = 0; mt < 2; mt++) {
                    mma16816(c[mt][2 * p],     a[mt], t4[0], t4[1]);
                    mma16816(c[mt][2 * p + 1], a[mt], t4[2], t4[3]);
                }
            }
        }
    }
#undef GPF
}

// QKV projection: outputs e4m3 (q,k: [B,H,S,D]; v: transposed [B,H,D,S])
__global__ void __launch_bounds__(256, 2) gemm_qkv(const float* __restrict__ bq,
                                                   const float* __restrict__ bk,
                                                   const float* __restrict__ bv) {
    extern __shared__ char gsm[];
    int z = blockIdx.z;
    int m0 = blockIdx.y * 128, n0 = blockIdx.x * 128;
    const float* bias = (z == 0) ? bq : (z == 1) ? bk : bv;

    float c[2][8][4];
    gemm_core(g_h, g_w + (size_t)z * CC * CC, m0, n0, c, gsm);

    int lane = threadIdx.x & 31;
    int wid = threadIdx.x >> 5;
    int wm = wid >> 1, wn = wid & 1;

    if (z < 2) {
        uint8_t* dst = (z == 0) ? g_q : g_k;
#pragma unroll
        for (int mt = 0; mt < 2; mt++) {
            int r0 = m0 + wm * 32 + mt * 16 + (lane >> 2);
            int b0i = r0 >> 11, s0i = r0 & 2047;
            int r1 = r0 + 8;
            int b1i = r1 >> 11, s1i = r1 & 2047;
#pragma unroll
            for (int nt = 0; nt < 8; nt++) {
                int n = n0 + wn * 64 + nt * 8 + (lane & 3) * 2;
                float bv0 = bias[n], bv1 = bias[n + 1];
                int h = n >> 6, d = n & 63;
                uint16_t v0 = f2e4m3x2(c[mt][nt][0] + bv0, c[mt][nt][1] + bv1);
                uint16_t v1 = f2e4m3x2(c[mt][nt][2] + bv0, c[mt][nt][3] + bv1);
                *(uint16_t*)&dst[(((size_t)b0i * HH + h) * SS + s0i) * DD + d] = v0;
                *(uint16_t*)&dst[(((size_t)b1i * HH + h) * SS + s1i) * DD + d] = v1;
            }
        }
    } else {
        // V: store transposed g_vt[((b*H+h)*D + d) * S + s], byte stores
#pragma unroll
        for (int mt = 0; mt < 2; mt++) {
            int r0 = m0 + wm * 32 + mt * 16 + (lane >> 2);
            int b0i = r0 >> 11, s0i = r0 & 2047;
            int r1 = r0 + 8;
            int b1i = r1 >> 11, s1i = r1 & 2047;
#pragma unroll
            for (int nt = 0; nt < 8; nt++) {
                int n = n0 + wn * 64 + nt * 8 + (lane & 3) * 2;
                float bv0 = bias[n], bv1 = bias[n + 1];
                int h = n >> 6, d = n & 63;
                size_t base0 = (((size_t)b0i * HH + h) * DD + d) * SS;
                size_t base1 = (((size_t)b1i * HH + h) * DD + d) * SS;
                uint16_t p0 = f2e4m3x2(c[mt][nt][0] + bv0, c[mt][nt][1] + bv1);
                uint16_t p1 = f2e4m3x2(c[mt][nt][2] + bv0, c[mt][nt][3] + bv1);
                g_vt[base0 + s0i]      = (uint8_t)(p0 & 0xFF);
                g_vt[base0 + SS + s0i] = (uint8_t)(p0 >> 8);
                g_vt[base1 + s1i]      = (uint8_t)(p1 & 0xFF);
                g_vt[base1 + SS + s1i] = (uint8_t)(p1 >> 8);
            }
        }
    }
}

// Output projection: fp32 out [B,C,S] = A@wo^T + bo + residual
__global__ void __launch_bounds__(256, 2) gemm_out(const float* __restrict__ bias,
                                                   const float* __restrict__ resid,
                                                   float* __restrict__ outp) {
    extern __shared__ char gsm[];
    int m0 = blockIdx.y * 128, n0 = blockIdx.x * 128;

    float c[2][8][4];
    gemm_core(g_o, g_w + (size_t)3 * CC * CC, m0, n0, c, gsm);

    int lane = threadIdx.x & 31;
    int wid = threadIdx.x >> 5;
    int wm = wid >> 1, wn = wid & 1;
#pragma unroll
    for (int mt = 0; mt < 2; mt++) {
        int r0 = m0 + wm * 32 + mt * 16 + (lane >> 2);
#pragma unroll
        for (int half = 0; half < 2; half++) {
            int m = r0 + half * 8;
            int b = m >> 11, s = m & 2047;
#pragma unroll
            for (int nt = 0; nt < 8; nt++) {
                int n = n0 + wn * 64 + nt * 8 + (lane & 3) * 2;
                size_t oi0 = ((size_t)b * CC + n) * SS + s;
                size_t oi1 = oi0 + SS;
                outp[oi0] = c[mt][nt][2 * half + 0] + bias[n]     + resid[oi0];
                outp[oi1] = c[mt][nt][2 * half + 1] + bias[n + 1] + resid[oi1];
            }
        }
    }
}

// ---------------- fp8 flash attention (no-rescale softmax) ----------------
// Q,K e4m3 [128 rows x 64 d] smem stride 80; V^T e4m3 [64 d x 128 keys] stride 144.
// P per-warp buffer [16 q x 32 keys] stride 80, warp-synchronous round-trip.
#define OFF_K 10240
#define OFF_V (10240 + 2 * 10240)          // 30720
#define OFF_P (30720 + 2 * 9216)           // 49152
#define A_SMEM_BYTES (49152 + 8 * 1280)    // 59392

__global__ void __launch_bounds__(256, 2) attn_mma() {
    extern __shared__ char asmem[];
    uint32_t sb0 = smem_u32(asmem);
    uint32_t sQ = sb0;
    uint32_t sK = sb0 + OFF_K;
    uint32_t sV = sb0 + OFF_V;

    int tid = threadIdx.x;
    int lane = tid & 31;
    int wid = tid >> 5;
    uint32_t sP = sb0 + OFF_P + (uint32_t)wid * 1280;
    int bh = blockIdx.y;
    int q0 = blockIdx.x * 128;

    const uint8_t* Qg = g_q + ((size_t)bh * SS + q0) * DD;
    const uint8_t* Kg = g_k + (size_t)bh * SS * DD;
    const uint8_t* Vg = g_vt + (size_t)bh * DD * SS;

    // K-load pattern: 2 threads/row (32B each); V: 4 threads/row (32B each)
    int kr = tid >> 1, kh = (tid & 1) * 32;
    const uint8_t* Kt = Kg + (size_t)kr * DD + kh;
    uint32_t kD = (uint32_t)kr * 80 + kh;
    int vr = tid >> 2, vq = (tid & 3) * 32;
    const uint8_t* Vt = Vg + (size_t)vr * SS + vq;
    uint32_t vD = (uint32_t)vr * 144 + vq;

    // prefetch K/V tile 0
    cp16(sK + kD, Kt);  cp16(sK + kD + 16, Kt + 16);
    cp16(sV + vD, Vt);  cp16(sV + vD + 16, Vt + 16);
    CP_COMMIT();

    // load Q tile [128 x 64] e4m3
    {
        const uint4* src = (const uint4*)(Qg + (size_t)kr * DD + kh);
        uint4* dst = (uint4*)(asmem + kD);
        dst[0] = src[0]; dst[1] = src[1];
    }
    __syncthreads();

    // Q fragments (k32 A-frags via b16 ldmatrix), constant across tiles
    uint32_t aq[2][4];
#pragma unroll
    for (int ch = 0; ch < 2; ch++) {
        uint32_t row = wid * 16 + (lane & 15);
        uint32_t addr = sQ + row * 80 + (lane >> 4) * 16 + ch * 32;
        ldsm4(aq[ch], addr);
    }

    float o[8][4];
#pragma unroll
    for (int i = 0; i < 8; i++)
#pragma unroll
        for (int j = 0; j < 4; j++) o[i][j] = 0.f;
    float l0 = 0.f, l1 = 0.f;

    uint32_t gg = (lane >> 2);        // row within 8
    uint32_t tt = (lane & 3) * 2;     // key pair offset

    for (int kt = 0; kt < 16; kt++) {
        uint32_t boK = (uint32_t)(kt & 1) * 10240;
        uint32_t boV = (uint32_t)(kt & 1) * 9216;
        CP_WAIT0();
        __syncthreads();
        if (kt < 15) {
            uint32_t bnK = (uint32_t)((kt + 1) & 1) * 10240;
            uint32_t bnV = (uint32_t)((kt + 1) & 1) * 9216;
            const uint8_t* Kn = Kt + (size_t)(kt + 1) * 128 * DD;
            const uint8_t* Vn = Vt + (size_t)(kt + 1) * 128;
            cp16(sK + bnK + kD, Kn);  cp16(sK + bnK + kD + 16, Kn + 16);
            cp16(sV + bnV + vD, Vn);  cp16(sV + bnV + vD + 16, Vn + 16);
            CP_COMMIT();
        }

#pragma unroll
        for (int s = 0; s < 8; s++) {
            // QK: 16 q x 16 keys, fp8 k32
            float c0[4] = {0.f, 0.f, 0.f, 0.f};
            float c1[4] = {0.f, 0.f, 0.f, 0.f};
#pragma unroll
            for (int ch = 0; ch < 2; ch++) {
                uint32_t t4[4];
                uint32_t addr = sK + boK + (uint32_t)(s * 16 + (lane & 15)) * 80
                              + (lane >> 4) * 16 + ch * 32;
                ldsm4(t4, addr);
                mma_fp8(c0, aq[ch], t4[0], t4[2]);
                mma_fp8(c1, aq[ch], t4[1], t4[3]);
            }
            float p00 = ex2(c0[0] * SC_LOG2E);
            float p01 = ex2(c0[1] * SC_LOG2E);
            float p02 = ex2(c0[2] * SC_LOG2E);
            float p03 = ex2(c0[3] * SC_LOG2E);
            float p10 = ex2(c1[0] * SC_LOG2E);
            float p11 = ex2(c1[1] * SC_LOG2E);
            float p12 = ex2(c1[2] * SC_LOG2E);
            float p13 = ex2(c1[3] * SC_LOG2E);
            l0 += p00 + p01 + p10 + p11;
            l1 += p02 + p03 + p12 + p13;
            // store P as e4m3 into per-warp buffer (local keys 0..31)
            uint32_t sbL = (uint32_t)(s & 1) * 16;
            uint32_t a0 = sP + gg * 80 + sbL + tt;
            uint32_t a1 = sP + (gg + 8) * 80 + sbL + tt;
            sts16(a0,     f2e4m3x2(p00, p01));
            sts16(a1,     f2e4m3x2(p02, p03));
            sts16(a0 + 8, f2e4m3x2(p10, p11));
            sts16(a1 + 8, f2e4m3x2(p12, p13));

            if (s & 1) {
                // PV over 32-key group
                __syncwarp();
                int gb = (s >> 1) * 32;
                uint32_t ap[4];
                ldsm4(ap, sP + (uint32_t)(lane & 15) * 80 + (lane >> 4) * 16);
#pragma unroll
                for (int dp = 0; dp < 4; dp++) {
                    uint32_t t4[4];
                    uint32_t addr = sV + boV + (uint32_t)(dp * 16 + (lane & 15)) * 144
                                  + gb + (lane >> 4) * 16;
                    ldsm4(t4, addr);
                    mma_fp8(o[2 * dp],     ap, t4[0], t4[2]);
                    mma_fp8(o[2 * dp + 1], ap, t4[1], t4[3]);
                }
                __syncwarp();
            }
        }
    }

    // reduce l over the 4-lane quad
    l0 += __shfl_xor_sync(0xFFFFFFFF, l0, 1);
    l0 += __shfl_xor_sync(0xFFFFFFFF, l0, 2);
    l1 += __shfl_xor_sync(0xFFFFFFFF, l1, 1);
    l1 += __shfl_xor_sync(0xFFFFFFFF, l1, 2);
    float invl0 = 1.f / l0, invl1 = 1.f / l1;

    // write O as bf16 to g_o [B,S,C]
    int b = bh >> 3, h = bh & 7;
    int row0 = q0 + wid * 16 + (lane >> 2);
    bf16* out0 = g_o + ((size_t)b * SS + row0) * CC + h * DD;
    bf16* out1 = g_o + ((size_t)b * SS + row0 + 8) * CC + h * DD;
#pragma unroll
    for (int nt = 0; nt < 8; nt++) {
        int d = nt * 8 + (lane & 3) * 2;
        *(uint32_t*)&out0[d] = pack_bf16x2(o[nt][0] * invl0, o[nt][1] * invl0);
        *(uint32_t*)&out1[d] = pack_bf16x2(o[nt][2] * invl1, o[nt][3] * invl1);
    }
}

// ---------------- launch ----------------
extern "C" void kernel_launch(void* const* d_in, const int* in_sizes, int n_in,
                              void* d_out, int out_size) {
    const float* x  = (const float*)d_in[0];
    const float* gw = (const float*)d_in[1];
    const float* gb = (const float*)d_in[2];
    const float* wq = (const float*)d_in[3];
    const float* bq = (const float*)d_in[4];
    const float* wk = (const float*)d_in[5];
    const float* bk = (const float*)d_in[6];
    const float* wv = (const float*)d_in[7];
    const float* bv = (const float*)d_in[8];
    const float* wo = (const float*)d_in[9];
    const float* bo = (const float*)d_in[10];
    float* out = (float*)d_out;

    cudaFuncSetAttribute(attn_mma, cudaFuncAttributeMaxDynamicSharedMemorySize, A_SMEM_BYTES);
    cudaFuncSetAttribute(gemm_qkv, cudaFuncAttributeMaxDynamicSharedMemorySize, G_SMEM_BYTES);
    cudaFuncSetAttribute(gemm_out, cudaFuncAttributeMaxDynamicSharedMemorySize, G_SMEM_BYTES);

    prep<<<128 + 1024, 256>>>(x, wq, wk, wv, wo);
    gn_finalize<<<1, 32>>>();
    norm_convert<<<dim3(SS / 32, CC / 32, BB), dim3(32, 32)>>>(x, gw, gb);

    gemm_qkv<<<dim3(CC / 128, BB * SS / 128, 3), 256, G_SMEM_BYTES>>>(bq, bk, bv);

    attn_mma<<<dim3(SS / 128, BB * HH), 256, A_SMEM_BYTES>>>();

    gemm_out<<<dim3(CC / 128, BB * SS / 128), 256, G_SMEM_BYTES>>>(bo, x, out);
}

// round 7
// speedup vs baseline: 1.0133x; 1.0133x over previous
#include <cuda_runtime.h>
#include <cuda_bf16.h>
#include <cstdint>
#include <math.h>

#define BB 4
#define CC 512
#define SS 2048
#define HH 8
#define DD 64
#define NPB (CC*SS)

typedef __nv_bfloat16 bf16;

// Q pre-scale: 0.125 (attention scale) * log2(e) so softmax p = ex2(score)
#define QPRESCALE 0.18033688011112042f

// ---------------- static device scratch ----------------
__device__ float g_part[128 * 2];
__device__ bf16 g_h[BB * SS * CC];         // normalized, [B,S,C]
__device__ bf16 g_w[4 * CC * CC];          // wq,wk,wv,wo bf16
__device__ bf16 g_q[BB * HH * SS * DD];    // [B,H,S,D] (pre-scaled)
__device__ bf16 g_k[BB * HH * SS * DD];
__device__ bf16 g_v[BB * HH * SS * DD];
__device__ bf16 g_o[BB * SS * CC];         // attention out, [B,S,C]

// ---------------- low-level helpers ----------------
__device__ __forceinline__ uint32_t smem_u32(const void* p) {
    uint32_t a;
    asm("{ .reg .u64 t; cvta.to.shared.u64 t, %1; cvt.u32.u64 %0, t; }" : "=r"(a) : "l"(p));
    return a;
}
__device__ __forceinline__ void ldsm4(uint32_t* r, uint32_t addr) {
    asm volatile("ldmatrix.sync.aligned.m8n8.x4.shared.b16 {%0,%1,%2,%3}, [%4];"
                 : "=r"(r[0]), "=r"(r[1]), "=r"(r[2]), "=r"(r[3]) : "r"(addr));
}
__device__ __forceinline__ void ldsm4t(uint32_t* r, uint32_t addr) {
    asm volatile("ldmatrix.sync.aligned.m8n8.x4.trans.shared.b16 {%0,%1,%2,%3}, [%4];"
                 : "=r"(r[0]), "=r"(r[1]), "=r"(r[2]), "=r"(r[3]) : "r"(addr));
}
__device__ __forceinline__ void mma16816(float* c, const uint32_t* a, uint32_t b0, uint32_t b1) {
    asm volatile("mma.sync.aligned.m16n8k16.row.col.f32.bf16.bf16.f32 "
                 "{%0,%1,%2,%3}, {%4,%5,%6,%7}, {%8,%9}, {%0,%1,%2,%3};"
                 : "+f"(c[0]), "+f"(c[1]), "+f"(c[2]), "+f"(c[3])
                 : "r"(a[0]), "r"(a[1]), "r"(a[2]), "r"(a[3]), "r"(b0), "r"(b1));
}
__device__ __forceinline__ uint32_t pack_bf16x2(float lo, float hi) {
    uint32_t r;
    asm("cvt.rn.bf16x2.f32 %0, %1, %2;" : "=r"(r) : "f"(hi), "f"(lo));
    return r;
}
__device__ __forceinline__ float ex2(float x) {
    float r;
    asm("ex2.approx.f32 %0, %1;" : "=f"(r) : "f"(x));
    return r;
}
__device__ __forceinline__ void cp16(uint32_t dst, const void* src) {
    asm volatile("cp.async.cg.shared.global [%0], [%1], 16;" :: "r"(dst), "l"(src));
}
#define CP_COMMIT() asm volatile("cp.async.commit_group;" ::: "memory")
#define CP_WAIT0()  asm volatile("cp.async.wait_group 0;" ::: "memory")
#define CP_WAIT1()  asm volatile("cp.async.wait_group 1;" ::: "memory")

// ---------------- fused: GroupNorm partials + weight bf16 convert ----------------
__global__ void prep(const float* __restrict__ x,
                     const float* __restrict__ wq, const float* __restrict__ wk,
                     const float* __restrict__ wv, const float* __restrict__ wo) {
    if (blockIdx.x >= 128) {
        int i = (blockIdx.x - 128) * 256 + threadIdx.x;
        g_w[0 * CC * CC + i] = __float2bfloat16(wq[i]);
        g_w[1 * CC * CC + i] = __float2bfloat16(wk[i]);
        g_w[2 * CC * CC + i] = __float2bfloat16(wv[i]);
        g_w[3 * CC * CC + i] = __float2bfloat16(wo[i]);
        return;
    }
    int b = blockIdx.x >> 5;
    int chunk = blockIdx.x & 31;
    const float4* p = (const float4*)(x + (size_t)b * NPB + (size_t)chunk * 32768);
    float s = 0.f, s2 = 0.f;
    for (int i = threadIdx.x; i < 8192; i += 256) {
        float4 v = p[i];
        s += v.x + v.y + v.z + v.w;
        s2 += v.x * v.x + v.y * v.y + v.z * v.z + v.w * v.w;
    }
    __shared__ float sh[256], sh2[256];
    sh[threadIdx.x] = s; sh2[threadIdx.x] = s2;
    __syncthreads();
    for (int off = 128; off > 0; off >>= 1) {
        if (threadIdx.x < off) {
            sh[threadIdx.x] += sh[threadIdx.x + off];
            sh2[threadIdx.x] += sh2[threadIdx.x + off];
        }
        __syncthreads();
    }
    if (threadIdx.x == 0) {
        g_part[blockIdx.x * 2 + 0] = sh[0];
        g_part[blockIdx.x * 2 + 1] = sh2[0];
    }
}

// ---------------- normalize + transpose (stats finalized in-block) ----------------
__global__ void norm_convert(const float* __restrict__ x,
                             const float* __restrict__ gw,
                             const float* __restrict__ gb) {
    __shared__ float tile[32][33];
    __shared__ float s_stats[2];
    int b = blockIdx.z;
    int c0 = blockIdx.y * 32;
    int s0 = blockIdx.x * 32;
    tile[threadIdx.y][threadIdx.x] =
        x[((size_t)b * CC + c0 + threadIdx.y) * SS + s0 + threadIdx.x];
    if (threadIdx.y == 0) {
        float s  = g_part[(b * 32 + threadIdx.x) * 2 + 0];
        float s2 = g_part[(b * 32 + threadIdx.x) * 2 + 1];
#pragma unroll
        for (int off = 16; off > 0; off >>= 1) {
            s  += __shfl_xor_sync(0xFFFFFFFF, s, off);
            s2 += __shfl_xor_sync(0xFFFFFFFF, s2, off);
        }
        if (threadIdx.x == 0) {
            float mean = s / (float)NPB;
            float var = s2 / (float)NPB - mean * mean;
            s_stats[0] = mean;
            s_stats[1] = rsqrtf(var + 1e-5f);
        }
    }
    __syncthreads();
    float mean = s_stats[0], inv = s_stats[1];
    int c = c0 + threadIdx.x;
    float scale = gw[c] * inv;
    float shift = gb[c] - mean * scale;
    float t = tile[threadIdx.x][threadIdx.y];
    g_h[((size_t)b * SS + s0 + threadIdx.y) * CC + c] = __float2bfloat16(t * scale + shift);
}

// ---------------- HMMA bf16 NT GEMM, K-tile 64, 3-stage cp.async ----------------
// block tile 128(M) x 128(N), 256 threads (8 warps: 4M x 2N -> 32x64 warp tile).
// 8 K-tiles of 64. Padded smem stride 72 bf16 (144B) -> conflict-free ldsm.
#define GSTR 72
#define GTB (128 * GSTR * 2)      // 18432 bytes per matrix per stage
#define G_SMEM_BYTES (6 * GTB)    // 3 stages x (A+B) = 110592

__device__ __forceinline__ void gemm_core(const bf16* __restrict__ A,
                                          const bf16* __restrict__ W,
                                          int m0, int n0, float c[2][8][4],
                                          char* smem) {
    int tid = threadIdx.x;
    int lane = tid & 31;
    int wid = tid >> 5;
    int wm = wid >> 1, wn = wid & 1;
    uint32_t sA = smem_u32(smem);
    uint32_t sB = sA + 3 * GTB;

#pragma unroll
    for (int i = 0; i < 2; i++)
#pragma unroll
        for (int j = 0; j < 8; j++)
#pragma unroll
            for (int k = 0; k < 4; k++) c[i][j][k] = 0.f;

    int r = tid >> 1;
    int half = (tid & 1) * 32;                       // elements
    const bf16* Ag = A + (size_t)(m0 + r) * 512 + half;
    const bf16* Wg = W + (size_t)(n0 + r) * 512 + half;
    uint32_t dOff = (uint32_t)r * 144 + (uint32_t)half * 2;

#define GPF(kt) do { \
        uint32_t _b = (uint32_t)((kt) % 3) * GTB; \
        const bf16* _An = Ag + (kt) * 64; \
        const bf16* _Wn = Wg + (kt) * 64; \
        cp16(sA + _b + dOff,      _An);      cp16(sA + _b + dOff + 16, _An + 8); \
        cp16(sA + _b + dOff + 32, _An + 16); cp16(sA + _b + dOff + 48, _An + 24); \
        cp16(sB + _b + dOff,      _Wn);      cp16(sB + _b + dOff + 16, _Wn + 8); \
        cp16(sB + _b + dOff + 32, _Wn + 16); cp16(sB + _b + dOff + 48, _Wn + 24); \
        CP_COMMIT(); \
    } while (0)

    GPF(0); GPF(1);

    for (int kt = 0; kt < 8; kt++) {
        CP_WAIT1();
        __syncthreads();
        if (kt < 6) GPF(kt + 2); else CP_COMMIT();
        uint32_t bo = (uint32_t)(kt % 3) * GTB;
#pragma unroll
        for (int ks = 0; ks < 4; ks++) {
            uint32_t a[2][4];
#pragma unroll
            for (int mt = 0; mt < 2; mt++) {
                uint32_t row = wm * 32 + mt * 16 + (lane & 15);
                uint32_t col = ks * 16 + (lane >> 4) * 8;
                ldsm4(a[mt], sA + bo + row * 144 + col * 2);
            }
#pragma unroll
            for (int p = 0; p < 4; p++) {
                uint32_t t4[4];
                uint32_t row = wn * 64 + p * 16 + (lane & 7) + ((lane >> 4) << 3);
                uint32_t col = ks * 16 + (((lane >> 3) & 1) << 3);
                ldsm4(t4, sB + bo + row * 144 + col * 2);
#pragma unroll
                for (int mt = 0; mt < 2; mt++) {
                    mma16816(c[mt][2 * p],     a[mt], t4[0], t4[1]);
                    mma16816(c[mt][2 * p + 1], a[mt], t4[2], t4[3]);
                }
            }
        }
    }
#undef GPF
}

// QKV projection: z selects weight/bias/dst. Output [B,H,S,D] bf16. Q pre-scaled.
__global__ void __launch_bounds__(256, 2) gemm_qkv(const float* __restrict__ bq,
                                                   const float* __restrict__ bk,
                                                   const float* __restrict__ bv) {
    extern __shared__ char gsm[];
    int z = blockIdx.z;
    int m0 = blockIdx.y * 128, n0 = blockIdx.x * 128;
    const float* bias = (z == 0) ? bq : (z == 1) ? bk : bv;
    bf16* dst = (z == 0) ? g_q : (z == 1) ? g_k : g_v;
    float qs = (z == 0) ? QPRESCALE : 1.0f;

    float c[2][8][4];
    gemm_core(g_h, g_w + (size_t)z * CC * CC, m0, n0, c, gsm);

    int lane = threadIdx.x & 31;
    int wid = threadIdx.x >> 5;
    int wm = wid >> 1, wn = wid & 1;
#pragma unroll
    for (int mt = 0; mt < 2; mt++) {
        int r0 = m0 + wm * 32 + mt * 16 + (lane >> 2);
        int b0i = r0 >> 11, s0i = r0 & 2047;
        int r1 = r0 + 8;
        int b1i = r1 >> 11, s1i = r1 & 2047;
#pragma unroll
        for (int nt = 0; nt < 8; nt++) {
            int n = n0 + wn * 64 + nt * 8 + (lane & 3) * 2;
            float bv0 = bias[n], bv1 = bias[n + 1];
            int h = n >> 6, d = n & 63;
            uint32_t v0 = pack_bf16x2((c[mt][nt][0] + bv0) * qs, (c[mt][nt][1] + bv1) * qs);
            uint32_t v1 = pack_bf16x2((c[mt][nt][2] + bv0) * qs, (c[mt][nt][3] + bv1) * qs);
            *(uint32_t*)&dst[(((size_t)b0i * HH + h) * SS + s0i) * DD + d] = v0;
            *(uint32_t*)&dst[(((size_t)b1i * HH + h) * SS + s1i) * DD + d] = v1;
        }
    }
}

// Output projection: fp32 out [B,C,S] = A@wo^T + bo + residual
__global__ void __launch_bounds__(256, 2) gemm_out(const float* __restrict__ bias,
                                                   const float* __restrict__ resid,
                                                   float* __restrict__ outp) {
    extern __shared__ char gsm[];
    int m0 = blockIdx.y * 128, n0 = blockIdx.x * 128;

    float c[2][8][4];
    gemm_core(g_o, g_w + (size_t)3 * CC * CC, m0, n0, c, gsm);

    int lane = threadIdx.x & 31;
    int wid = threadIdx.x >> 5;
    int wm = wid >> 1, wn = wid & 1;
#pragma unroll
    for (int mt = 0; mt < 2; mt++) {
        int r0 = m0 + wm * 32 + mt * 16 + (lane >> 2);
#pragma unroll
        for (int half = 0; half < 2; half++) {
            int m = r0 + half * 8;
            int b = m >> 11, s = m & 2047;
#pragma unroll
            for (int nt = 0; nt < 8; nt++) {
                int n = n0 + wn * 64 + nt * 8 + (lane & 3) * 2;
                size_t oi0 = ((size_t)b * CC + n) * SS + s;
                size_t oi1 = oi0 + SS;
                outp[oi0] = c[mt][nt][2 * half + 0] + bias[n]     + resid[oi0];
                outp[oi1] = c[mt][nt][2 * half + 1] + bias[n + 1] + resid[oi1];
            }
        }
    }
}

// ---------------- bf16 flash attention, 2-slab interleaved ----------------
// CTA = 128 q rows of one (b,h); 8 warps x 16 q rows. 128-key double-buffered
// cp.async K/V tiles. Q pre-scaled -> P = ex2(S). Two 16-key slabs processed
// with interleaved mma streams for ILP. P packed directly into A-fragments.
#define AST 72
#define ATB (128 * AST * 2)           // 18432 bytes per tile buffer
#define A_SMEM_BYTES (5 * ATB)        // Q + K0 + K1 + V0 + V1

__global__ void __launch_bounds__(256, 2) attn_mma() {
    extern __shared__ char asmem[];
    uint32_t sQ = smem_u32(asmem);
    uint32_t sK = sQ + ATB;
    uint32_t sV = sQ + 3 * ATB;

    int tid = threadIdx.x;
    int lane = tid & 31;
    int wid = tid >> 5;
    int bh = blockIdx.y;
    int q0 = blockIdx.x * 128;

    const bf16* Qg = g_q + ((size_t)bh * SS + q0) * DD;
    const bf16* Kg = g_k + (size_t)bh * SS * DD;
    const bf16* Vg = g_v + (size_t)bh * SS * DD;

    int r = tid >> 1, cseg = (tid & 1) * 32;
    uint32_t dOff = (uint32_t)(r * AST + cseg) * 2;
    const bf16* Kt = Kg + (size_t)r * DD + cseg;
    const bf16* Vt = Vg + (size_t)r * DD + cseg;

    // prefetch K/V tile 0 into buffer 0
#pragma unroll
    for (int j = 0; j < 4; j++) {
        cp16(sK + dOff + j * 16, Kt + j * 8);
        cp16(sV + dOff + j * 16, Vt + j * 8);
    }
    CP_COMMIT();

    // load Q tile [128 x 64]
    {
        const uint4* src = (const uint4*)(Qg + (size_t)r * DD + cseg);
        uint4* dst = (uint4*)(asmem + dOff);
        dst[0] = src[0]; dst[1] = src[1]; dst[2] = src[2]; dst[3] = src[3];
    }
    __syncthreads();

    // preload Q fragments (constant across key tiles)
    uint32_t aq[4][4];
#pragma unroll
    for (int ks = 0; ks < 4; ks++) {
        uint32_t row = wid * 16 + (lane & 15);
        uint32_t col = ks * 16 + (lane >> 4) * 8;
        ldsm4(aq[ks], sQ + (row * AST + col) * 2);
    }

    float o[8][4];
#pragma unroll
    for (int i = 0; i < 8; i++)
#pragma unroll
        for (int j = 0; j < 4; j++) o[i][j] = 0.f;
    float l0 = 0.f, l1 = 0.f;

    for (int kt = 0; kt < 16; kt++) {
        uint32_t bo = (uint32_t)(kt & 1) * ATB;
        CP_WAIT0();
        __syncthreads();
        if (kt < 15) {
            uint32_t bn = (uint32_t)((kt + 1) & 1) * ATB;
            const bf16* Kn = Kt + (size_t)(kt + 1) * 128 * DD;
            const bf16* Vn = Vt + (size_t)(kt + 1) * 128 * DD;
#pragma unroll
            for (int j = 0; j < 4; j++) {
                cp16(sK + bn + dOff + j * 16, Kn + j * 8);
                cp16(sV + bn + dOff + j * 16, Vn + j * 8);
            }
            CP_COMMIT();
        }

#pragma unroll
        for (int sp = 0; sp < 4; sp++) {
            // two 16-key slabs, interleaved mma streams
            uint32_t rowa = (uint32_t)(sp * 32);
            uint32_t rowb = rowa + 16;
            float ca0[4] = {0.f,0.f,0.f,0.f}, ca1[4] = {0.f,0.f,0.f,0.f};
            float cb0[4] = {0.f,0.f,0.f,0.f}, cb1[4] = {0.f,0.f,0.f,0.f};
#pragma unroll
            for (int ks = 0; ks < 4; ks++) {
                uint32_t ta[4], tb[4];
                uint32_t rsub = (lane & 7) + ((lane >> 4) << 3);
                uint32_t col = ks * 16 + (((lane >> 3) & 1) << 3);
                ldsm4(ta, sK + bo + ((rowa + rsub) * AST + col) * 2);
                ldsm4(tb, sK + bo + ((rowb + rsub) * AST + col) * 2);
                mma16816(ca0, aq[ks], ta[0], ta[1]);
                mma16816(cb0, aq[ks], tb[0], tb[1]);
                mma16816(ca1, aq[ks], ta[2], ta[3]);
                mma16816(cb1, aq[ks], tb[2], tb[3]);
            }
            float pa00 = ex2(ca0[0]), pa01 = ex2(ca0[1]);
            float pa02 = ex2(ca0[2]), pa03 = ex2(ca0[3]);
            float pa10 = ex2(ca1[0]), pa11 = ex2(ca1[1]);
            float pa12 = ex2(ca1[2]), pa13 = ex2(ca1[3]);
            float pb00 = ex2(cb0[0]), pb01 = ex2(cb0[1]);
            float pb02 = ex2(cb0[2]), pb03 = ex2(cb0[3]);
            float pb10 = ex2(cb1[0]), pb11 = ex2(cb1[1]);
            float pb12 = ex2(cb1[2]), pb13 = ex2(cb1[3]);
            l0 += pa00 + pa01 + pa10 + pa11 + pb00 + pb01 + pb10 + pb11;
            l1 += pa02 + pa03 + pa12 + pa13 + pb02 + pb03 + pb12 + pb13;
            uint32_t apa[4], apb[4];
            apa[0] = pack_bf16x2(pa00, pa01);
            apa[1] = pack_bf16x2(pa02, pa03);
            apa[2] = pack_bf16x2(pa10, pa11);
            apa[3] = pack_bf16x2(pa12, pa13);
            apb[0] = pack_bf16x2(pb00, pb01);
            apb[1] = pack_bf16x2(pb02, pb03);
            apb[2] = pack_bf16x2(pb10, pb11);
            apb[3] = pack_bf16x2(pb12, pb13);
#pragma unroll
            for (int dp = 0; dp < 4; dp++) {
                uint32_t tva[4], tvb[4];
                uint32_t rsub = (lane & 15);
                uint32_t colv = dp * 16 + (lane >> 4) * 8;
                ldsm4t(tva, sV + bo + ((rowa + rsub) * AST + colv) * 2);
                ldsm4t(tvb, sV + bo + ((rowb + rsub) * AST + colv) * 2);
                mma16816(o[2 * dp],     apa, tva[0], tva[1]);
                mma16816(o[2 * dp + 1], apa, tva[2], tva[3]);
                mma16816(o[2 * dp],     apb, tvb[0], tvb[1]);
                mma16816(o[2 * dp + 1], apb, tvb[2], tvb[3]);
            }
        }
    }

    // reduce l over the 4-lane quad (lanes sharing a row)
    l0 += __shfl_xor_sync(0xFFFFFFFF, l0, 1);
    l0 += __shfl_xor_sync(0xFFFFFFFF, l0, 2);
    l1 += __shfl_xor_sync(0xFFFFFFFF, l1, 1);
    l1 += __shfl_xor_sync(0xFFFFFFFF, l1, 2);
    float invl0 = 1.f / l0, invl1 = 1.f / l1;

    // write O as bf16 to g_o [B,S,C]
    int b = bh >> 3, h = bh & 7;
    int row0 = q0 + wid * 16 + (lane >> 2);
    bf16* out0 = g_o + ((size_t)b * SS + row0) * CC + h * DD;
    bf16* out1 = g_o + ((size_t)b * SS + row0 + 8) * CC + h * DD;
#pragma unroll
    for (int nt = 0; nt < 8; nt++) {
        int d = nt * 8 + (lane & 3) * 2;
        *(uint32_t*)&out0[d] = pack_bf16x2(o[nt][0] * invl0, o[nt][1] * invl0);
        *(uint32_t*)&out1[d] = pack_bf16x2(o[nt][2] * invl1, o[nt][3] * invl1);
    }
}

// ---------------- launch ----------------
extern "C" void kernel_launch(void* const* d_in, const int* in_sizes, int n_in,
                              void* d_out, int out_size) {
    const float* x  = (const float*)d_in[0];
    const float* gw = (const float*)d_in[1];
    const float* gb = (const float*)d_in[2];
    const float* wq = (const float*)d_in[3];
    const float* bq = (const float*)d_in[4];
    const float* wk = (const float*)d_in[5];
    const float* bk = (const float*)d_in[6];
    const float* wv = (const float*)d_in[7];
    const float* bv = (const float*)d_in[8];
    const float* wo = (const float*)d_in[9];
    const float* bo = (const float*)d_in[10];
    float* out = (float*)d_out;

    cudaFuncSetAttribute(attn_mma, cudaFuncAttributeMaxDynamicSharedMemorySize, A_SMEM_BYTES);
    cudaFuncSetAttribute(gemm_qkv, cudaFuncAttributeMaxDynamicSharedMemorySize, G_SMEM_BYTES);
    cudaFuncSetAttribute(gemm_out, cudaFuncAttributeMaxDynamicSharedMemorySize, G_SMEM_BYTES);

    prep<<<128 + 1024, 256>>>(x, wq, wk, wv, wo);
    norm_convert<<<dim3(SS / 32, CC / 32, BB), dim3(32, 32)>>>(x, gw, gb);

    gemm_qkv<<<dim3(CC / 128, BB * SS / 128, 3), 256, G_SMEM_BYTES>>>(bq, bk, bv);

    attn_mma<<<dim3(SS / 128, BB * HH), 256, A_SMEM_BYTES>>>();

    gemm_out<<<dim3(CC / 128, BB * SS / 128), 256, G_SMEM_BYTES>>>(bo, x, out);
}